// round 1
// baseline (speedup 1.0000x reference)
#include <cuda_runtime.h>
#include <mma.h>
#include <cstdint>

using namespace nvcuda;

// Problem constants (fixed by the reference)
#define K_DIM 4096   // in_features
#define N_DIM 4096   // out_features
#define GROUPS 32    // K_DIM / 128

// 64 MB dequantized-weight scratch, row-major [N][K] (w[n][k])
__device__ float g_w[(size_t)N_DIM * K_DIM];

// ---------------------------------------------------------------------------
// Kernel 1: unpack int4 -> fp32, fully coalesced (1 thread per packed int32)
// ---------------------------------------------------------------------------
__global__ __launch_bounds__(256) void dequant_kernel(
    const int* __restrict__ qw,     // [N, K/8]
    const int* __restrict__ qz,     // [N, GROUPS/8]
    const float* __restrict__ sc)   // [N, GROUPS]
{
    int idx = blockIdx.x * blockDim.x + threadIdx.x;   // 0 .. N*K/8
    if (idx >= N_DIM * (K_DIM / 8)) return;
    int n  = idx >> 9;        // / (K_DIM/8 = 512)
    int k8 = idx & 511;
    int g  = k8 >> 4;         // group = (k8*8)/128

    unsigned v  = (unsigned)qw[idx];
    unsigned zv = (unsigned)qz[(n << 2) + (g >> 3)];
    float z = (float)((zv >> ((g & 7) * 4)) & 15u);
    float s = sc[(n << 5) + g];

    float o[8];
#pragma unroll
    for (int j = 0; j < 8; j++)
        o[j] = ((float)((v >> (4 * j)) & 15u) - z) * s;

    float4* dst = (float4*)(g_w + (size_t)n * K_DIM + (size_t)k8 * 8);
    dst[0] = make_float4(o[0], o[1], o[2], o[3]);
    dst[1] = make_float4(o[4], o[5], o[6], o[7]);
}

// ---------------------------------------------------------------------------
// Kernel 2: tiled TF32 WMMA GEMM: out[m][n] = sum_k x[m][k]*w[n][k] + bias[n]
// Block tile 128x128, BK=32. 8 warps: 2(M) x 4(N), warp tile 64x32.
// ---------------------------------------------------------------------------
#define BM 128
#define BN 128
#define BK 32
#define LDT 36            // padded smem row stride (floats), 16B-aligned rows

__global__ __launch_bounds__(256, 2) void gemm_tf32_kernel(
    const float* __restrict__ A,      // x [M, K]
    const float* __restrict__ bias,   // [N]
    float* __restrict__ C)            // [M, N]
{
    __shared__ float As[BM * LDT];
    __shared__ float Bs[BN * LDT];
    __shared__ float Cw[8][16 * 16];  // per-warp epilogue staging

    const float* __restrict__ B = g_w;

    int tid  = threadIdx.x;
    int wid  = tid >> 5;
    int lane = tid & 31;
    int warp_m = wid & 1;      // 0..1
    int warp_n = wid >> 1;     // 0..3
    int bm = blockIdx.y * BM;
    int bn = blockIdx.x * BN;

    wmma::fragment<wmma::accumulator, 16, 16, 8, float> acc[4][2];
#pragma unroll
    for (int i = 0; i < 4; i++)
#pragma unroll
        for (int j = 0; j < 2; j++)
            wmma::fill_fragment(acc[i][j], 0.0f);

    int r  = tid >> 3;   // 0..31 (tile row within 32-row pass)
    int c4 = tid & 7;    // float4 column within BK

    for (int kt = 0; kt < K_DIM; kt += BK) {
        // ---- global -> shared (coalesced float4) ----
#pragma unroll
        for (int i = 0; i < 4; i++) {
            int row = r + i * 32;
            float4 va = *(const float4*)(A + (size_t)(bm + row) * K_DIM + kt + c4 * 4);
            *(float4*)(As + row * LDT + c4 * 4) = va;
            float4 vb = *(const float4*)(B + (size_t)(bn + row) * K_DIM + kt + c4 * 4);
            *(float4*)(Bs + row * LDT + c4 * 4) = vb;
        }
        __syncthreads();

        // ---- compute 4 k-steps of k=8 ----
#pragma unroll
        for (int ks = 0; ks < BK; ks += 8) {
            wmma::fragment<wmma::matrix_a, 16, 16, 8, wmma::precision::tf32, wmma::row_major> af[4];
            wmma::fragment<wmma::matrix_b, 16, 16, 8, wmma::precision::tf32, wmma::col_major> bf[2];
#pragma unroll
            for (int i = 0; i < 4; i++) {
                wmma::load_matrix_sync(af[i], As + (warp_m * 64 + i * 16) * LDT + ks, LDT);
#pragma unroll
                for (int t = 0; t < af[i].num_elements; t++)
                    af[i].x[t] = wmma::__float_to_tf32(af[i].x[t]);
            }
#pragma unroll
            for (int j = 0; j < 2; j++) {
                // Bs holds w[n][k]; col_major B fragment reads element (k,n) at ptr[n*ldm + k]
                wmma::load_matrix_sync(bf[j], Bs + (warp_n * 32 + j * 16) * LDT + ks, LDT);
#pragma unroll
                for (int t = 0; t < bf[j].num_elements; t++)
                    bf[j].x[t] = wmma::__float_to_tf32(bf[j].x[t]);
            }
#pragma unroll
            for (int i = 0; i < 4; i++)
#pragma unroll
                for (int j = 0; j < 2; j++)
                    wmma::mma_sync(acc[i][j], af[i], bf[j], acc[i][j]);
        }
        __syncthreads();
    }

    // ---- epilogue: exact fp32 bias add via per-warp smem staging ----
    int rr = lane >> 1;          // 0..15
    int cc = (lane & 1) * 8;     // 0 or 8
#pragma unroll
    for (int i = 0; i < 4; i++) {
#pragma unroll
        for (int j = 0; j < 2; j++) {
            wmma::store_matrix_sync(&Cw[wid][0], acc[i][j], 16, wmma::mem_row_major);
            __syncwarp();
            int gm = bm + warp_m * 64 + i * 16 + rr;
            int gn = bn + warp_n * 32 + j * 16 + cc;
            float4 o0, o1;
            o0.x = Cw[wid][rr * 16 + cc + 0] + bias[gn + 0];
            o0.y = Cw[wid][rr * 16 + cc + 1] + bias[gn + 1];
            o0.z = Cw[wid][rr * 16 + cc + 2] + bias[gn + 2];
            o0.w = Cw[wid][rr * 16 + cc + 3] + bias[gn + 3];
            o1.x = Cw[wid][rr * 16 + cc + 4] + bias[gn + 4];
            o1.y = Cw[wid][rr * 16 + cc + 5] + bias[gn + 5];
            o1.z = Cw[wid][rr * 16 + cc + 6] + bias[gn + 6];
            o1.w = Cw[wid][rr * 16 + cc + 7] + bias[gn + 7];
            *(float4*)(C + (size_t)gm * N_DIM + gn)     = o0;
            *(float4*)(C + (size_t)gm * N_DIM + gn + 4) = o1;
            __syncwarp();
        }
    }
}

// ---------------------------------------------------------------------------
extern "C" void kernel_launch(void* const* d_in, const int* in_sizes, int n_in,
                              void* d_out, int out_size)
{
    const float* x    = (const float*)d_in[0];
    const int*   qw   = (const int*)d_in[1];
    const int*   qz   = (const int*)d_in[2];
    const float* sc   = (const float*)d_in[3];
    const float* bias = (const float*)d_in[4];
    float* out = (float*)d_out;

    int tokens = in_sizes[0] / K_DIM;   // 4096

    // 1) dequantize weights into g_w
    int nthreads = N_DIM * (K_DIM / 8);
    dequant_kernel<<<(nthreads + 255) / 256, 256>>>(qw, qz, sc);

    // 2) TF32 GEMM + bias
    dim3 grid(N_DIM / BN, tokens / BM);
    gemm_tf32_kernel<<<grid, 256>>>(x, bias, out);
}

// round 6
// speedup vs baseline: 5.1358x; 5.1358x over previous
#include <cuda_runtime.h>
#include <cuda_fp16.h>
#include <cstdint>

// Problem constants (fixed)
#define K_DIM 4096
#define N_DIM 4096
#define M_DIM 4096
#define GROUPS 32

// fp16 scratch: dequantized weights [N,K] and converted activations [M,K]
__device__ __half g_w[(size_t)N_DIM * K_DIM];
__device__ __half g_x[(size_t)M_DIM * K_DIM];

// ---------------------------------------------------------------------------
// Prep 1: int4 -> fp16 dequant (coalesced, 1 thread per packed int32 -> 16B)
// ---------------------------------------------------------------------------
__global__ __launch_bounds__(256) void dequant_kernel(
    const int* __restrict__ qw, const int* __restrict__ qz,
    const float* __restrict__ sc)
{
    int idx = blockIdx.x * blockDim.x + threadIdx.x;
    if (idx >= N_DIM * (K_DIM / 8)) return;
    int n = idx >> 9;          // / 512
    int k8 = idx & 511;
    int g = k8 >> 4;

    unsigned v = (unsigned)qw[idx];
    unsigned zv = (unsigned)qz[(n << 2) + (g >> 3)];
    float z = (float)((zv >> ((g & 7) * 4)) & 15u);
    float s = sc[(n << 5) + g];

    __half2 h[4];
#pragma unroll
    for (int j = 0; j < 4; j++) {
        float lo = ((float)((v >> (8 * j)) & 15u) - z) * s;
        float hi = ((float)((v >> (8 * j + 4)) & 15u) - z) * s;
        h[j] = __floats2half2_rn(lo, hi);
    }
    *(uint4*)(g_w + (size_t)n * K_DIM + (size_t)k8 * 8) = *(uint4*)h;
}

// ---------------------------------------------------------------------------
// Prep 2: x fp32 -> fp16 (8 elements per thread)
// ---------------------------------------------------------------------------
__global__ __launch_bounds__(256) void convx_kernel(const float* __restrict__ x, int n8)
{
    int i = blockIdx.x * blockDim.x + threadIdx.x;
    if (i >= n8) return;
    float4 a = ((const float4*)x)[i * 2];
    float4 b = ((const float4*)x)[i * 2 + 1];
    __half2 h[4];
    h[0] = __floats2half2_rn(a.x, a.y);
    h[1] = __floats2half2_rn(a.z, a.w);
    h[2] = __floats2half2_rn(b.x, b.y);
    h[3] = __floats2half2_rn(b.z, b.w);
    ((uint4*)g_x)[i] = *(uint4*)h;
}

// ---------------------------------------------------------------------------
// fp16 mma.sync GEMM: C[m][n] = sum_k x[m][k]*w[n][k] + bias[n]
// BM=BN=128, BK=32, 4-stage cp.async, 8 warps, warp tile 64(M) x 32(N)
// smem rows: 64B (32 halves), XOR swizzle chunk^((row>>1)&3) -> conflict-free
// ---------------------------------------------------------------------------
#define BM 128
#define BN 128
#define BK 32
#define STAGES 4
#define K_ITERS (K_DIM / BK)
#define STAGE_BYTES 16384          // A 8KB + B 8KB
#define SMEM_TOTAL (STAGES * STAGE_BYTES)

__device__ __forceinline__ uint32_t smem_u32(const void* p) {
    uint32_t a;
    asm("{ .reg .u64 t; cvta.to.shared.u64 t, %1; cvt.u32.u64 %0, t; }" : "=r"(a) : "l"(p));
    return a;
}

__device__ __forceinline__ void ldm_x4(uint32_t* r, uint32_t addr) {
    asm volatile("ldmatrix.sync.aligned.m8n8.x4.shared.b16 {%0,%1,%2,%3}, [%4];"
                 : "=r"(r[0]), "=r"(r[1]), "=r"(r[2]), "=r"(r[3]) : "r"(addr));
}

__device__ __forceinline__ void mma16816(float* d, const uint32_t* a,
                                         uint32_t b0, uint32_t b1) {
    asm volatile(
        "mma.sync.aligned.m16n8k16.row.col.f32.f16.f16.f32 "
        "{%0,%1,%2,%3}, {%4,%5,%6,%7}, {%8,%9}, {%0,%1,%2,%3};"
        : "+f"(d[0]), "+f"(d[1]), "+f"(d[2]), "+f"(d[3])
        : "r"(a[0]), "r"(a[1]), "r"(a[2]), "r"(a[3]), "r"(b0), "r"(b1));
}

__device__ __forceinline__ void load_stage(uint32_t sb, int slot, int kt,
                                           int bm, int bn, int tid)
{
    uint32_t st = sb + slot * STAGE_BYTES;
#pragma unroll
    for (int h = 0; h < 2; h++) {
        int ci = tid + h * 256;            // 0..511
        int row = ci >> 2;                 // 0..127
        int c = ci & 3;                    // 16B chunk within 64B row
        uint32_t sw = (uint32_t)(row * 64 + ((c ^ ((row >> 1) & 3)) << 4));
        const __half* ga = g_x + (size_t)(bm + row) * K_DIM + kt + c * 8;
        asm volatile("cp.async.cg.shared.global [%0], [%1], 16;"
                     :: "r"(st + sw), "l"(ga) : "memory");
        const __half* gb = g_w + (size_t)(bn + row) * K_DIM + kt + c * 8;
        asm volatile("cp.async.cg.shared.global [%0], [%1], 16;"
                     :: "r"(st + 8192 + sw), "l"(gb) : "memory");
    }
}

__global__ __launch_bounds__(256, 2) void gemm_hmma_kernel(
    const float* __restrict__ bias, float* __restrict__ C)
{
    extern __shared__ char smem[];
    uint32_t sb = smem_u32(smem);
    int tid = threadIdx.x;
    int lane = tid & 31;
    int wid = tid >> 5;
    int warp_m = wid & 1;       // 2 M-slots of 64
    int warp_n = wid >> 1;      // 4 N-slots of 32
    int bm = blockIdx.y * BM;
    int bn = blockIdx.x * BN;

    // ldmatrix per-lane row/chunk decomposition
    int ar = (lane & 7) + ((lane >> 3) & 1) * 8;   // A row within 16
    int acb = lane >> 4;                            // A k16-chunk half (0/1)
    int br = (lane & 7) + ((lane >> 4) & 1) * 8;   // B n-row within 16
    int bcb = (lane >> 3) & 1;                      // B k16-chunk half

    float acc[4][4][4];
#pragma unroll
    for (int i = 0; i < 4; i++)
#pragma unroll
        for (int j = 0; j < 4; j++)
#pragma unroll
            for (int t = 0; t < 4; t++) acc[i][j][t] = 0.0f;

    // prologue: stages 0..2
#pragma unroll
    for (int p = 0; p < STAGES - 1; p++) {
        load_stage(sb, p, p * BK, bm, bn, tid);
        asm volatile("cp.async.commit_group;" ::: "memory");
    }

    for (int it = 0; it < K_ITERS; ++it) {
        asm volatile("cp.async.wait_group 2;" ::: "memory");
        __syncthreads();

        int nxt = it + STAGES - 1;
        if (nxt < K_ITERS) {
            load_stage(sb, nxt & (STAGES - 1), nxt * BK, bm, bn, tid);
            asm volatile("cp.async.commit_group;" ::: "memory");
        }

        uint32_t Ab = sb + (it & (STAGES - 1)) * STAGE_BYTES;
        uint32_t Bb = Ab + 8192;

#pragma unroll
        for (int ks = 0; ks < 2; ks++) {
            uint32_t a[4][4];
#pragma unroll
            for (int mt = 0; mt < 4; mt++) {
                int row = warp_m * 64 + mt * 16 + ar;
                uint32_t addr = Ab + row * 64 +
                    (((ks * 2 + acb) ^ ((row >> 1) & 3)) << 4);
                ldm_x4(a[mt], addr);
            }
            uint32_t b[2][4];
#pragma unroll
            for (int np = 0; np < 2; np++) {
                int row = warp_n * 32 + np * 16 + br;
                uint32_t addr = Bb + row * 64 +
                    (((ks * 2 + bcb) ^ ((row >> 1) & 3)) << 4);
                ldm_x4(b[np], addr);
            }
#pragma unroll
            for (int mt = 0; mt < 4; mt++)
#pragma unroll
                for (int nt = 0; nt < 4; nt++)
                    mma16816(acc[mt][nt], a[mt],
                             b[nt >> 1][(nt & 1) * 2], b[nt >> 1][(nt & 1) * 2 + 1]);
        }
    }

    // epilogue: direct fp32 stores + bias
    int gr = lane >> 2;
    int gc = (lane & 3) * 2;
#pragma unroll
    for (int mt = 0; mt < 4; mt++) {
#pragma unroll
        for (int nt = 0; nt < 4; nt++) {
            int row = bm + warp_m * 64 + mt * 16 + gr;
            int col = bn + warp_n * 32 + nt * 8 + gc;
            float b0 = __ldg(bias + col);
            float b1 = __ldg(bias + col + 1);
            float2 v0 = make_float2(acc[mt][nt][0] + b0, acc[mt][nt][1] + b1);
            float2 v1 = make_float2(acc[mt][nt][2] + b0, acc[mt][nt][3] + b1);
            *(float2*)(C + (size_t)row * N_DIM + col) = v0;
            *(float2*)(C + (size_t)(row + 8) * N_DIM + col) = v1;
        }
    }
}

// ---------------------------------------------------------------------------
extern "C" void kernel_launch(void* const* d_in, const int* in_sizes, int n_in,
                              void* d_out, int out_size)
{
    const float* x    = (const float*)d_in[0];
    const int*   qw   = (const int*)d_in[1];
    const int*   qz   = (const int*)d_in[2];
    const float* sc   = (const float*)d_in[3];
    const float* bias = (const float*)d_in[4];
    float* out = (float*)d_out;

    int tokens = in_sizes[0] / K_DIM;   // 4096

    int nth = N_DIM * (K_DIM / 8);
    dequant_kernel<<<(nth + 255) / 256, 256>>>(qw, qz, sc);
    int n8 = tokens * K_DIM / 8;
    convx_kernel<<<(n8 + 255) / 256, 256>>>(x, n8);

    cudaFuncSetAttribute(gemm_hmma_kernel,
                         cudaFuncAttributeMaxDynamicSharedMemorySize, SMEM_TOTAL);
    dim3 grid(N_DIM / BN, tokens / BM);
    gemm_hmma_kernel<<<grid, 256, SMEM_TOTAL>>>(bias, out);
}